// round 4
// baseline (speedup 1.0000x reference)
#include <cuda_runtime.h>
#include <cstdint>

#define BB   64
#define LL   128
#define TE   256
#define CIN  256
#define HH   512
#define CAT  768
#define G4   2048
#define OUTN 128
#define NBLK 256
#define NTHR 256

// ---------------- persistent device buffers ----------------
__device__ float g_pe[(size_t)BB * TE * HH];   // proj_enc (32 MB)
__device__ float g_pdp[32 * 64 * HH];          // pd split-K partials (32 slices)
__device__ float g_xp[24 * 64 * CIN];          // xhat partials (x:0-7, ctx:8-23)
__device__ float g_zp[16 * 64 * G4];           // lstm-z partials (h:0-7, x:8-15)
__device__ float g_fp[24 * 64 * 3 * HH];       // cfc partials (h:0-15, x:16-23)
__device__ float g_h[BB * HH];
__device__ float g_c[BB * HH];
__device__ float g_ctx[BB * HH];
__device__ float g_xhat[BB * CIN];
__device__ float g_hlstm[BB * HH];
__device__ float g_hid[BB * HH];
__device__ float g_w6[G4 * CAT];               // [W_ih | W_hh], gate-major rows
__device__ float g_w3[3 * HH * CAT];           // [W_ff1 ; W_ff2 ; W_ta+W_tb]
__device__ float g_b3[3 * HH];
__device__ unsigned g_bcnt;
__device__ unsigned g_bgen;

// ---------------- helpers ----------------
__device__ __forceinline__ float fast_tanh(float x) {
    float y;
    asm("tanh.approx.f32 %0, %1;" : "=f"(y) : "f"(x));
    return y;
}
__device__ __forceinline__ float sigm(float x) {
    return 1.0f / (1.0f + __expf(-x));
}

// ---------------- global barrier (all NBLK blocks co-resident) ----------------
__device__ __forceinline__ void gsync() {
    __syncthreads();
    if (threadIdx.x == 0) {
        unsigned gen = atomicAdd(&g_bgen, 0u);
        __threadfence();
        if (atomicAdd(&g_bcnt, 1u) == NBLK - 1) {
            g_bcnt = 0;
            __threadfence();
            atomicAdd(&g_bgen, 1u);
        } else {
            while (atomicAdd(&g_bgen, 0u) == gen) { __nanosleep(128); }
        }
        __threadfence();
    }
    __syncthreads();
}

// ---------------- shared memory union ----------------
struct SmemG { float X[32][68]; float W[32][132]; };
struct SmemA { float pds[HH]; float wss[HH]; float se[TE]; float ss[TE]; float red[NTHR]; };
union Smem { SmemG g; SmemA a; };

// ---------------- 64x128 GEMM tile, 256 threads, 8x4 thread tile ----------------
// X row m: cols [0,K0) from X0 + m*str0, cols [K0,...) from X1 + m*str1.
// W row-major (wstr). Output tile cols n0..n0+127. klen % 32 == 0, kbeg % 32 == 0,
// K0 % 32 == 0 (each 32-chunk entirely on one side of the concat).
__device__ __noinline__ void gemm_t(const float* __restrict__ X0, int K0, int str0,
                                    const float* __restrict__ X1, int str1,
                                    const float* __restrict__ W, int wstr, int n0,
                                    int kbeg, int klen,
                                    float* __restrict__ dst, int dstr,
                                    const float* __restrict__ bias, SmemG& s) {
    const int tid = threadIdx.x;
    const int m  = tid >> 2, q = tid & 3;        // X loader: row m, k-octet q
    const int n  = tid >> 3, c = tid & 7;        // W loader
    const int tx = tid & 31, ty = tid >> 5;      // compute
    float xr[8], wreg[16];
    float acc[8][4] = {};

    auto loadregs = [&](int kg0) {
        int kg = kg0 + q * 8;
        const float* xs = (kg < K0) ? (X0 + (size_t)m * str0 + kg)
                                    : (X1 + (size_t)m * str1 + (kg - K0));
        float4 v0 = *(const float4*)xs;
        float4 v1 = *(const float4*)(xs + 4);
        xr[0] = v0.x; xr[1] = v0.y; xr[2] = v0.z; xr[3] = v0.w;
        xr[4] = v1.x; xr[5] = v1.y; xr[6] = v1.z; xr[7] = v1.w;
#pragma unroll
        for (int r = 0; r < 4; r++) {
            const float* wrp = W + (size_t)(n0 + n + 32 * r) * wstr + kg0;
#pragma unroll
            for (int i = 0; i < 4; i++) wreg[r * 4 + i] = wrp[c + 8 * i];
        }
    };

    loadregs(kbeg);
    for (int kb = 0; kb < klen; kb += 32) {
#pragma unroll
        for (int j = 0; j < 8; j++) s.X[q * 8 + j][m] = xr[j];
#pragma unroll
        for (int r = 0; r < 4; r++)
#pragma unroll
            for (int i = 0; i < 4; i++) s.W[c + 8 * i][n + 32 * r] = wreg[r * 4 + i];
        __syncthreads();
        if (kb + 32 < klen) loadregs(kbeg + kb + 32);
#pragma unroll
        for (int k = 0; k < 32; k++) {
            float4 bv = *(const float4*)&s.W[k][tx * 4];
            float4 a0 = *(const float4*)&s.X[k][ty * 8];
            float4 a1 = *(const float4*)&s.X[k][ty * 8 + 4];
            const float av[8] = {a0.x, a0.y, a0.z, a0.w, a1.x, a1.y, a1.z, a1.w};
#pragma unroll
            for (int r = 0; r < 8; r++) {
                acc[r][0] += av[r] * bv.x;
                acc[r][1] += av[r] * bv.y;
                acc[r][2] += av[r] * bv.z;
                acc[r][3] += av[r] * bv.w;
            }
        }
        __syncthreads();
    }
#pragma unroll
    for (int r = 0; r < 8; r++) {
        int mm = ty * 8 + r;
        int nn = n0 + tx * 4;
        float4 v = make_float4(acc[r][0], acc[r][1], acc[r][2], acc[r][3]);
        if (bias) {
            v.x += bias[nn]; v.y += bias[nn + 1]; v.z += bias[nn + 2]; v.w += bias[nn + 3];
        }
        *(float4*)(dst + (size_t)mm * dstr + nn) = v;
    }
}

// ---------------- per-batch attention (one block per batch) ----------------
__device__ __noinline__ void attention(int b, const float* __restrict__ h_en,
                                       const float* __restrict__ w_score, SmemA& a) {
    const int tid = threadIdx.x;
    // reduce pd partials (32 slices)
    for (int h = tid; h < HH; h += NTHR) {
        float sacc = 0.0f;
#pragma unroll
        for (int sl = 0; sl < 32; sl++)
            sacc += g_pdp[(size_t)(sl * 64 + b) * HH + h];
        a.pds[h] = sacc;
        a.wss[h] = w_score[h];
    }
    __syncthreads();
    // e scores: 8 warps, 32 t's each
    const int warp = tid >> 5, lane = tid & 31;
    const float4* pds4 = (const float4*)a.pds;
    const float4* wss4 = (const float4*)a.wss;
    for (int tt = 0; tt < 32; tt++) {
        int t = warp + 8 * tt;
        const float4* pe4 = (const float4*)(g_pe + ((size_t)b * TE + t) * HH);
        float acc = 0.0f;
#pragma unroll
        for (int i = 0; i < 4; i++) {
            int h4 = lane + 32 * i;
            float4 p = pe4[h4];
            float4 d = pds4[h4];
            float4 w = wss4[h4];
            acc += w.x * fast_tanh(p.x + d.x);
            acc += w.y * fast_tanh(p.y + d.y);
            acc += w.z * fast_tanh(p.z + d.z);
            acc += w.w * fast_tanh(p.w + d.w);
        }
#pragma unroll
        for (int off = 16; off > 0; off >>= 1)
            acc += __shfl_down_sync(0xffffffffu, acc, off);
        if (lane == 0) a.se[t] = acc;
    }
    __syncthreads();
    // softmax over TE=256 with 256 threads
    float ev = a.se[tid];
    a.red[tid] = ev;
    __syncthreads();
    for (int s = 128; s > 0; s >>= 1) {
        if (tid < s) a.red[tid] = fmaxf(a.red[tid], a.red[tid + s]);
        __syncthreads();
    }
    float mx = a.red[0];
    __syncthreads();
    float p = __expf(ev - mx);
    a.red[tid] = p;
    __syncthreads();
    for (int s = 128; s > 0; s >>= 1) {
        if (tid < s) a.red[tid] += a.red[tid + s];
        __syncthreads();
    }
    float inv = 1.0f / a.red[0];
    a.ss[tid] = p * inv;
    __syncthreads();
    // context: ctx[m] = sum_t ss[t]*h_en[b,t,m], m in two halves
    for (int m = tid; m < HH; m += NTHR) {
        const float* hb = h_en + (size_t)b * TE * HH + m;
        float a0 = 0, a1 = 0, a2 = 0, a3 = 0;
        for (int t = 0; t < TE; t += 4) {
            a0 += a.ss[t + 0] * hb[(size_t)(t + 0) * HH];
            a1 += a.ss[t + 1] * hb[(size_t)(t + 1) * HH];
            a2 += a.ss[t + 2] * hb[(size_t)(t + 2) * HH];
            a3 += a.ss[t + 3] * hb[(size_t)(t + 3) * HH];
        }
        g_ctx[b * HH + m] = (a0 + a1) + (a2 + a3);
    }
}

// ---------------- weight packing (separate small kernel) ----------------
__global__ void k_pack(const float* __restrict__ W_ih, const float* __restrict__ W_hh,
                       const float* __restrict__ W_ff1, const float* __restrict__ W_ff2,
                       const float* __restrict__ W_ta, const float* __restrict__ W_tb,
                       const float* __restrict__ b_ff1, const float* __restrict__ b_ff2,
                       const float* __restrict__ b_ta, const float* __restrict__ b_tb) {
    const int N6 = G4 * CAT;
    const int N3 = 3 * HH * CAT;
    const int NB2 = 3 * HH;
    int total = N6 + N3 + NB2;
    for (int i = blockIdx.x * blockDim.x + threadIdx.x; i < total; i += gridDim.x * blockDim.x) {
        if (i < N6) {
            int nn = i / CAT, k = i % CAT;
            g_w6[i] = (k < CIN) ? W_ih[nn * CIN + k] : W_hh[nn * HH + (k - CIN)];
        } else if (i < N6 + N3) {
            int j = i - N6;
            int nn = j / CAT, k = j % CAT;
            int gate = nn / HH, u = nn % HH;
            float v;
            if (gate == 0)      v = W_ff1[u * CAT + k];
            else if (gate == 1) v = W_ff2[u * CAT + k];
            else                v = W_ta[u * CAT + k] + W_tb[u * CAT + k];
            g_w3[j] = v;
        } else {
            int nn = i - N6 - N3;
            int gate = nn / HH, u = nn % HH;
            g_b3[nn] = (gate == 0) ? b_ff1[u] : (gate == 1) ? b_ff2[u] : (b_ta[u] + b_tb[u]);
        }
    }
}

// ---------------- the persistent uber-kernel ----------------
__global__ void __launch_bounds__(NTHR, 2)
k_main(const float* __restrict__ x, const float* __restrict__ h_en,
       const float* __restrict__ W_dec, const float* __restrict__ W_enc,
       const float* __restrict__ b_enc, const float* __restrict__ w_score,
       const float* __restrict__ W_yattn, const float* __restrict__ b_yattn,
       const float* __restrict__ b_ih,
       const float* __restrict__ W_o1, const float* __restrict__ b_o1,
       const float* __restrict__ W_o2, const float* __restrict__ b_o2,
       float* __restrict__ out, int write_state) {
    __shared__ Smem sm;
    const int bid = blockIdx.x;
    const int tid = threadIdx.x;
    const int gstep = NBLK * NTHR;

    // ---- P0: init h,c + proj_enc (16384x512 = h_en @ W_enc^T + b) ----
    for (int idx = bid * NTHR + tid; idx < BB * HH; idx += gstep) {
        g_h[idx] = 0.0f; g_c[idx] = 0.0f;
    }
    for (int j = bid; j < 1024; j += NBLK) {           // 256 m-tiles x 4 n-tiles
        int mt = j >> 2, nt = j & 3;
        gemm_t(h_en + (size_t)mt * 64 * HH, HH, HH, h_en, 0,
               W_enc, HH, nt * 128, 0, HH,
               g_pe + (size_t)mt * 64 * HH, HH, b_enc, sm.g);
    }
    gsync();

    for (int t = 0; t < LL; t++) {
        const float* xt = x + (size_t)t * CIN;
        // ---- P1: pd split-K (4 ntiles x 32 slices k32) + xhat x-part (2 x 8) ----
        for (int j = bid; j < 144; j += NBLK) {
            if (j < 128) {
                int nt = j >> 5, ks = j & 31;
                gemm_t(g_h, HH, HH, g_c, HH,
                       W_dec, 1024, nt * 128, ks * 32, 32,
                       g_pdp + (size_t)ks * 64 * HH, HH, nullptr, sm.g);
            } else {
                int qj = j - 128;
                int nt = qj >> 3, ks = qj & 7;
                gemm_t(xt, CIN, LL * CIN, xt, 0,
                       W_yattn, CAT, nt * 128, ks * 32, 32,
                       g_xp + (size_t)ks * 64 * CIN, CIN, nullptr, sm.g);
            }
        }
        gsync();
        // ---- P2: attention (blocks 0-63) || z h-part (16 ntiles x 8 slices k64) ----
        if (bid < 64) {
            attention(bid, h_en, w_score, sm.a);
        } else {
            for (int j = bid - 64; j < 128; j += NBLK - 64) {
                int nt = j >> 3, ks = j & 7;
                gemm_t(g_xhat, CIN, CIN, g_h, HH,
                       g_w6, CAT, nt * 128, CIN + ks * 64, 64,
                       g_zp + (size_t)ks * 64 * G4, G4, nullptr, sm.g);
            }
        }
        gsync();
        // ---- P3: xhat ctx-part (2 ntiles x 16 slices k32 -> slices 8..23) ----
        for (int j = bid; j < 32; j += NBLK) {
            int nt = j >> 4, ks = j & 15;
            gemm_t(xt, CIN, LL * CIN, g_ctx, HH,
                   W_yattn, CAT, nt * 128, CIN + ks * 32, 32,
                   g_xp + (size_t)(8 + ks) * 64 * CIN, CIN, nullptr, sm.g);
        }
        gsync();
        // ---- P4: reduce xhat (24 slices) + bias ----
        for (int idx = bid * NTHR + tid; idx < BB * CIN; idx += gstep) {
            int m = idx >> 8, nn = idx & 255;
            float s = b_yattn[nn];
#pragma unroll
            for (int sl = 0; sl < 24; sl++)
                s += g_xp[(size_t)(sl * 64 + m) * CIN + nn];
            g_xhat[idx] = s;
        }
        gsync();
        // ---- P5: z x-part (16x8 k32 -> slices 8..15) + cfc x-part (12x8 k32 -> slices 16..23) ----
        for (int j = bid; j < 224; j += NBLK) {
            if (j < 128) {
                int nt = j >> 3, ks = j & 7;
                gemm_t(g_xhat, CIN, CIN, g_h, HH,
                       g_w6, CAT, nt * 128, ks * 32, 32,
                       g_zp + (size_t)(8 + ks) * 64 * G4, G4, nullptr, sm.g);
            } else {
                int qj = j - 128;
                int nt = qj >> 3, ks = qj & 7;
                gemm_t(g_xhat, CIN, CIN, g_hlstm, HH,
                       g_w3, CAT, nt * 128, ks * 32, 32,
                       g_fp + (size_t)(16 + ks) * 64 * 3 * HH, 3 * HH, nullptr, sm.g);
            }
        }
        gsync();
        // ---- P6: reduce z (16 slices) + LSTM pointwise ----
        for (int idx = bid * NTHR + tid; idx < BB * HH; idx += gstep) {
            int m = idx >> 9, u = idx & 511;
            float zi = b_ih[u], zg = b_ih[u + 512], zf = b_ih[u + 1024], zo = b_ih[u + 1536];
#pragma unroll
            for (int sl = 0; sl < 16; sl++) {
                const float* p = g_zp + (size_t)(sl * 64 + m) * G4;
                zi += p[u]; zg += p[u + 512]; zf += p[u + 1024]; zo += p[u + 1536];
            }
            float c_old = g_c[idx];
            float nc = c_old * sigm(zf + 1.0f) + tanhf(zi) * sigm(zg);
            g_c[idx] = nc;
            g_hlstm[idx] = tanhf(nc) * sigm(zo);
        }
        gsync();
        // ---- P7: cfc h-part (12 ntiles x 16 slices k32 -> slices 0..15) ----
        for (int j = bid; j < 192; j += NBLK) {
            int nt = j >> 4, ks = j & 15;
            gemm_t(g_xhat, CIN, CIN, g_hlstm, HH,
                   g_w3, CAT, nt * 128, CIN + ks * 32, 32,
                   g_fp + (size_t)ks * 64 * 3 * HH, 3 * HH, nullptr, sm.g);
        }
        gsync();
        // ---- P8: reduce cfc (24 slices) + pointwise -> new h ----
        for (int idx = bid * NTHR + tid; idx < BB * HH; idx += gstep) {
            int m = idx >> 9, u = idx & 511;
            float f1 = g_b3[u], f2 = g_b3[u + 512], tg = g_b3[u + 1024];
#pragma unroll
            for (int sl = 0; sl < 24; sl++) {
                const float* p = g_fp + (size_t)(sl * 64 + m) * (3 * HH);
                f1 += p[u]; f2 += p[u + 512]; tg += p[u + 1024];
            }
            float ti = sigm(tg);
            g_h[idx] = tanhf(f1) * (1.0f - ti) + ti * tanhf(f2);
        }
        gsync();
    }

    // ---- E1: O1 GEMM ([h|ctx], K=1024): 4 ntiles x 16 slices k64 -> zp ----
    for (int j = bid; j < 64; j += NBLK) {
        int nt = j >> 4, ks = j & 15;
        gemm_t(g_h, HH, HH, g_ctx, HH,
               W_o1, 1024, nt * 128, ks * 64, 64,
               g_zp + (size_t)ks * 64 * HH, HH, nullptr, sm.g);
    }
    gsync();
    // ---- E2: reduce + leaky relu -> g_hid ----
    for (int idx = bid * NTHR + tid; idx < BB * HH; idx += gstep) {
        int m = idx >> 9, u = idx & 511;
        float s = b_o1[u];
#pragma unroll
        for (int sl = 0; sl < 16; sl++)
            s += g_zp[(size_t)(sl * 64 + m) * HH + u];
        g_hid[idx] = (s > 0.0f) ? s : 0.01f * s;
    }
    gsync();
    // ---- E3: O2 GEMM (hid, K=512): 1 ntile x 8 slices k64 -> fp ----
    for (int j = bid; j < 8; j += NBLK) {
        int ks = j;
        gemm_t(g_hid, HH, HH, g_hid, 0,
               W_o2, HH, 0, ks * 64, 64,
               g_fp + (size_t)ks * 64 * OUTN, OUTN, nullptr, sm.g);
    }
    gsync();
    // ---- E4: final reduce + bias (+ optional state copy) ----
    for (int idx = bid * NTHR + tid; idx < BB * OUTN; idx += gstep) {
        int m = idx >> 7, u = idx & 127;
        float s = b_o2[u];
#pragma unroll
        for (int sl = 0; sl < 8; sl++)
            s += g_fp[(size_t)(sl * 64 + m) * OUTN + u];
        out[idx] = s;
    }
    if (write_state) {
        for (int idx = bid * NTHR + tid; idx < BB * HH; idx += gstep) {
            out[BB * OUTN + idx] = g_h[idx];
            out[BB * OUTN + BB * HH + idx] = g_c[idx];
        }
    }
}

// ============================================================================
extern "C" void kernel_launch(void* const* d_in, const int* in_sizes, int n_in,
                              void* d_out, int out_size) {
    const float* x       = (const float*)d_in[0];
    const float* h_en    = (const float*)d_in[1];
    const float* W_dec   = (const float*)d_in[2];
    const float* W_enc   = (const float*)d_in[3];
    const float* b_enc   = (const float*)d_in[4];
    const float* w_score = (const float*)d_in[5];
    const float* W_yattn = (const float*)d_in[6];
    const float* b_yattn = (const float*)d_in[7];
    const float* W_ih    = (const float*)d_in[8];
    const float* b_ih    = (const float*)d_in[9];
    const float* W_hh    = (const float*)d_in[10];
    const float* W_ff1   = (const float*)d_in[11];
    const float* b_ff1   = (const float*)d_in[12];
    const float* W_ff2   = (const float*)d_in[13];
    const float* b_ff2   = (const float*)d_in[14];
    const float* W_ta    = (const float*)d_in[15];
    const float* b_ta    = (const float*)d_in[16];
    const float* W_tb    = (const float*)d_in[17];
    const float* b_tb    = (const float*)d_in[18];
    const float* W_o1    = (const float*)d_in[19];
    const float* b_o1    = (const float*)d_in[20];
    const float* W_o2    = (const float*)d_in[21];
    const float* b_o2    = (const float*)d_in[22];
    float* out = (float*)d_out;

    int write_state = (out_size >= BB * OUTN + 2 * BB * HH) ? 1 : 0;

    k_pack<<<512, 256>>>(W_ih, W_hh, W_ff1, W_ff2, W_ta, W_tb,
                         b_ff1, b_ff2, b_ta, b_tb);
    k_main<<<NBLK, NTHR>>>(x, h_en, W_dec, W_enc, b_enc, w_score,
                           W_yattn, b_yattn, b_ih, W_o1, b_o1, W_o2, b_o2,
                           out, write_state);
}